// round 6
// baseline (speedup 1.0000x reference)
#include <cuda_runtime.h>
#include <cuda_fp16.h>
#include <math.h>
#include <stdint.h>

#define T 8
#define NN 100000
#define H 128
#define NIN 64
#define LN_EPS 1e-5f
#define WSCALE 64.f
#define WSCALE_INV 0.015625f

// ---------------- folded weights in mma-B-fragment layout (hi-only) --------
// slot idx = ((nt*KT+kt)*32+lane)*4 + grp*2 + p   (uint2 per lane-slot)
// nt=n/8 (global 0..15), kt=k/16, lane=((n&7)<<2)|((k>>1)&3), grp=(k>>3)&1, p=k&1
__device__ __align__(8) __half g_wqF[16*8*32*4];
__device__ __align__(8) __half g_wkF[16*8*32*4];
__device__ __align__(8) __half g_wvF[16*8*32*4];
__device__ __align__(8) __half g_wrF[16*4*32*4];
__device__ float g_cq[T*H], g_ck[T*H], g_cv[T*H];   // [t][c]
__device__ float g_hb[T*H];
__device__ float g_tmpVP[H*H];
__device__ float g_cvt[T*H];

template<int KT>
__device__ __forceinline__ void writeFrag(__half* wf, int n, int k, float w) {
    int nt = n >> 3, kt = k >> 4;
    int lane = ((n & 7) << 2) | ((k >> 1) & 3);
    int grp = (k >> 3) & 1, p = k & 1;
    wf[((nt*KT + kt)*32 + lane)*4 + grp*2 + p] = __float2half_rn(WSCALE * w);
}

// ---------------- prep kernels ----------------
__global__ void prep0_kernel(const float* __restrict__ proj_b) {
    int t = blockIdx.x, m = threadIdx.x;
    int i2 = m & ~1;
    double div = exp((double)i2 * (-log(100000.0)) / (double)H);
    double arg = (double)(t + 1) * div;
    double pe = (m & 1) ? cos(arg) : sin(arg);
    g_hb[t*H + m] = proj_b[m] + (float)pe;
}

__global__ void prep1_kernel(const float* __restrict__ proj_w,
                             const float* __restrict__ q_w,
                             const float* __restrict__ k_w,
                             const float* __restrict__ v_w,
                             const float* __restrict__ res_w) {
    int c = blockIdx.x, j = threadIdx.x;
    float sq = 0.f, sk = 0.f, sv = 0.f;
    for (int m = 0; m < H; m++) {
        float p = proj_w[m*H + j];
        sq = fmaf(q_w[c*H + m], p, sq);
        sk = fmaf(k_w[c*H + m], p, sk);
        sv = fmaf(v_w[c*H + m], p, sv);
    }
    writeFrag<8>(g_wqF, c, j, sq);
    writeFrag<8>(g_wkF, c, j, sk);
    g_tmpVP[c*H + j] = sv;
    if (j < NIN) writeFrag<4>(g_wrF, c, j, res_w[c*NIN + j]);
    if (j < T) {
        float a = 0.f, b = 0.f, vv = 0.f;
        for (int m = 0; m < H; m++) {
            float hb = g_hb[j*H + m];
            a  = fmaf(q_w[c*H + m], hb, a);
            b  = fmaf(k_w[c*H + m], hb, b);
            vv = fmaf(v_w[c*H + m], hb, vv);
        }
        g_cq[j*H + c] = a;
        g_ck[j*H + c] = b;
        g_cvt[j*H + c] = vv;
    }
}

__global__ void prep2_kernel(const float* __restrict__ fc_w) {
    int c = blockIdx.x, j = threadIdx.x;
    float s = 0.f;
    for (int m = 0; m < H; m++) s = fmaf(fc_w[c*H + m], g_tmpVP[m*H + j], s);
    writeFrag<8>(g_wvF, c, j, s);
    if (j < T) {
        float s2 = 0.f;
        for (int m = 0; m < H; m++) s2 = fmaf(fc_w[c*H + m], g_cvt[j*H + m], s2);
        g_cv[j*H + c] = s2;
    }
}

// ---------------- mma helpers ----------------
__device__ __forceinline__ void mma16816(float* c, const uint32_t* a,
                                         uint32_t b0, uint32_t b1) {
    asm volatile(
        "mma.sync.aligned.m16n8k16.row.col.f32.f16.f16.f32 "
        "{%0,%1,%2,%3},{%4,%5,%6,%7},{%8,%9},{%0,%1,%2,%3};\n"
        : "+f"(c[0]), "+f"(c[1]), "+f"(c[2]), "+f"(c[3])
        : "r"(a[0]), "r"(a[1]), "r"(a[2]), "r"(a[3]), "r"(b0), "r"(b1));
}

__device__ __forceinline__ uint32_t pack2(__half a, __half b) {
    __half2 t = __halves2half2(a, b);
    return *reinterpret_cast<uint32_t*>(&t);
}

// warp GEMM: 16 rows x 64 cols (ntBase..ntBase+7), K=KT*16, 2-pass fp32 accum
template<int KT>
__device__ __forceinline__ void wgemm(float acc[8][4], const float* aP,
                                      const __half* wf, int lane, int ntBase) {
    const uint2* w2 = (const uint2*)wf;
#pragma unroll
    for (int kt = 0; kt < KT; kt++) {
        uint32_t ahi[4], alo[4];
#pragma unroll
        for (int p = 0; p < 4; p++) {
            float2 v = *(const float2*)(aP + (kt*4 + p)*64 + lane*2);
            __half hx = __float2half_rn(v.x), hy = __float2half_rn(v.y);
            ahi[p] = pack2(hx, hy);
            alo[p] = pack2(__float2half_rn(v.x - __half2float(hx)),
                           __float2half_rn(v.y - __half2float(hy)));
        }
        uint2 b[8];
#pragma unroll
        for (int nt = 0; nt < 8; nt++) {
            b[nt] = __ldg(&w2[((ntBase + nt)*KT + kt)*32 + lane]);
            mma16816(acc[nt], ahi, b[nt].x, b[nt].y);
        }
#pragma unroll
        for (int nt = 0; nt < 8; nt++)
            mma16816(acc[nt], alo, b[nt].x, b[nt].y);
    }
}

__device__ __forceinline__ void scale_bias(float acc[8][4],
                                           const float* __restrict__ cb,
                                           int tq, int col0) {
#pragma unroll
    for (int nt = 0; nt < 8; nt++) {
        float2 b = __ldg((const float2*)(cb + tq*H + col0 + nt*8));
        acc[nt][0] = acc[nt][0]*WSCALE_INV + b.x;
        acc[nt][1] = acc[nt][1]*WSCALE_INV + b.y;
        acc[nt][2] = acc[nt][2]*WSCALE_INV + b.x;
        acc[nt][3] = acc[nt][3]*WSCALE_INV + b.y;
    }
}

// ---- main: 8 nodes/CTA, 8 warps, pair of warps = 2 nodes (64 cols each) ---
__global__ void __launch_bounds__(256, 2) htgnn_main(
    const float* __restrict__ inter, const float* __restrict__ x,
    const float* __restrict__ fc_b, const float* __restrict__ res_b,
    const float* __restrict__ res_alpha, const float* __restrict__ ln_g,
    const float* __restrict__ ln_b, float* __restrict__ out)
{
    extern __shared__ __align__(16) float aS[];   // [4][2048] A tiles
    float* dS  = aS + 8192;                       // score partials, 1024 f
    float* lnS = aS + 9216;                       // LN partials, 256 f
    const int tid = threadIdx.x;
    const int w = tid >> 5, lane = tid & 31;
    const int pair = w >> 1, h = w & 1;
    const int q = lane >> 2, j = lane & 3;
    const int node0 = blockIdx.x * 8;
    const int na = node0 + 2*pair, nb = na + 1;
    const int ntBase = h * 8;
    const int col0 = h*64 + j*2;
    float* aP = aS + pair*2048;
    const unsigned FULL = 0xffffffffu;

    // ---- stage inter frags: warp-half h writes kt = h*4 .. h*4+3 ----
#pragma unroll
    for (int kk = 0; kk < 4; kk++) {
        int kt = h*4 + kk;
#pragma unroll
        for (int p = 0; p < 4; p++) {
            int node = (p & 1) ? nb : na;
            int k = kt*16 + ((p >> 1) & 1)*8 + j*2;
            *(float2*)(aP + (kt*4 + p)*64 + lane*2) =
                *(const float2*)(inter + ((size_t)q*NN + node)*H + k);
        }
    }
    __syncthreads();

    // ---- Q, K over own 64 cols ----
    float qacc[8][4] = {};
    wgemm<8>(qacc, aP, g_wqF, lane, ntBase);
    scale_bias(qacc, g_cq, q, col0);
    float kacc[8][4] = {};
    wgemm<8>(kacc, aP, g_wkF, lane, ntBase);
    scale_bias(kacc, g_ck, q, col0);

    // ---- partial dots over own 64 cols; exchange halves via SMEM ----
    float sa[8], sb[8];
#pragma unroll
    for (int s = 0; s < 8; s++) {
        int src = (((q + s) & 7) << 2) | j;
        float da = 0.f, db = 0.f;
#pragma unroll
        for (int nt = 0; nt < 8; nt++) {
            da = fmaf(qacc[nt][0], __shfl_sync(FULL, kacc[nt][0], src), da);
            da = fmaf(qacc[nt][1], __shfl_sync(FULL, kacc[nt][1], src), da);
            db = fmaf(qacc[nt][2], __shfl_sync(FULL, kacc[nt][2], src), db);
            db = fmaf(qacc[nt][3], __shfl_sync(FULL, kacc[nt][3], src), db);
        }
        da += __shfl_xor_sync(FULL, da, 1);
        da += __shfl_xor_sync(FULL, da, 2);
        db += __shfl_xor_sync(FULL, db, 1);
        db += __shfl_xor_sync(FULL, db, 2);
        sa[s] = da; sb[s] = db;
    }
    if (j == 0) {
        int bi = ((pair*2 + h)*8 + q)*16;
#pragma unroll
        for (int s = 0; s < 8; s++) {
            dS[bi + s*2]     = sa[s];
            dS[bi + s*2 + 1] = sb[s];
        }
    }
    __syncthreads();
    {
        int oi = ((pair*2 + (1 - h))*8 + q)*16;
#pragma unroll
        for (int s = 0; s < 8; s++) {
            sa[s] += dS[oi + s*2];
            sb[s] += dS[oi + s*2 + 1];
        }
    }

    // ---- softmax (per lane; sa[s] = score[q, (q+s)&7]) ----
    float pa[8], pb[8];
    {
        float ma = sa[0], mb = sb[0];
#pragma unroll
        for (int s = 1; s < 8; s++) { ma = fmaxf(ma, sa[s]); mb = fmaxf(mb, sb[s]); }
        float za = 0.f, zb = 0.f;
#pragma unroll
        for (int s = 0; s < 8; s++) {
            pa[s] = expf(sa[s] - ma); za += pa[s];
            pb[s] = expf(sb[s] - mb); zb += pb[s];
        }
        float ia = 1.f/za, ib = 1.f/zb;
#pragma unroll
        for (int s = 0; s < 8; s++) { pa[s] *= ia; pb[s] *= ib; }
    }

    // ---- V (fc folded) over own 64 cols ----
    float vacc[8][4] = {};
    wgemm<8>(vacc, aP, g_wvF, lane, ntBase);
    scale_bias(vacc, g_cv, q, col0);

    // ---- O = S @ V (warp-local shfl) ----
    float oacc[8][4] = {};
#pragma unroll
    for (int s = 0; s < 8; s++) {
        int src = (((q + s) & 7) << 2) | j;
        float wa = pa[s], wb = pb[s];
#pragma unroll
        for (int nt = 0; nt < 8; nt++) {
            oacc[nt][0] = fmaf(wa, __shfl_sync(FULL, vacc[nt][0], src), oacc[nt][0]);
            oacc[nt][1] = fmaf(wa, __shfl_sync(FULL, vacc[nt][1], src), oacc[nt][1]);
            oacc[nt][2] = fmaf(wb, __shfl_sync(FULL, vacc[nt][2], src), oacc[nt][2]);
            oacc[nt][3] = fmaf(wb, __shfl_sync(FULL, vacc[nt][3], src), oacc[nt][3]);
        }
    }

    // ---- stage x frags (after ALL pair reads of aP are done) ----
    __syncthreads();
#pragma unroll
    for (int kk = 0; kk < 2; kk++) {
        int kt = h*2 + kk;
#pragma unroll
        for (int p = 0; p < 4; p++) {
            int node = (p & 1) ? nb : na;
            int k = kt*16 + ((p >> 1) & 1)*8 + j*2;
            *(float2*)(aP + (kt*4 + p)*64 + lane*2) =
                *(const float2*)(x + ((size_t)q*NN + node)*NIN + k);
        }
    }
    __syncthreads();
    float racc[8][4] = {};
    wgemm<4>(racc, aP, g_wrF, lane, ntBase);

    // ---- epilogue: relu/gate, LN partials + exchange, normalize, store ----
    float alpha = 1.f / (1.f + expf(-__ldg(res_alpha)));
    float beta = 1.f - alpha;
    float sua = 0.f, sqa = 0.f, sub = 0.f, sqb = 0.f;
#pragma unroll
    for (int nt = 0; nt < 8; nt++) {
        int c = col0 + nt*8;
        float2 fb = __ldg((const float2*)(fc_b + c));
        float2 rb = __ldg((const float2*)(res_b + c));
        float v0 = fmaxf(oacc[nt][0] + fb.x, 0.f)*alpha +
                   (racc[nt][0]*WSCALE_INV + rb.x)*beta;
        float v1 = fmaxf(oacc[nt][1] + fb.y, 0.f)*alpha +
                   (racc[nt][1]*WSCALE_INV + rb.y)*beta;
        float v2 = fmaxf(oacc[nt][2] + fb.x, 0.f)*alpha +
                   (racc[nt][2]*WSCALE_INV + rb.x)*beta;
        float v3 = fmaxf(oacc[nt][3] + fb.y, 0.f)*alpha +
                   (racc[nt][3]*WSCALE_INV + rb.y)*beta;
        oacc[nt][0] = v0; oacc[nt][1] = v1; oacc[nt][2] = v2; oacc[nt][3] = v3;
        sua += v0 + v1; sqa += v0*v0 + v1*v1;
        sub += v2 + v3; sqb += v2*v2 + v3*v3;
    }
    sua += __shfl_xor_sync(FULL, sua, 1); sua += __shfl_xor_sync(FULL, sua, 2);
    sqa += __shfl_xor_sync(FULL, sqa, 1); sqa += __shfl_xor_sync(FULL, sqa, 2);
    sub += __shfl_xor_sync(FULL, sub, 1); sub += __shfl_xor_sync(FULL, sub, 2);
    sqb += __shfl_xor_sync(FULL, sqb, 1); sqb += __shfl_xor_sync(FULL, sqb, 2);
    if (j == 0) {
        int bi = ((pair*2 + h)*8 + q)*4;
        lnS[bi] = sua; lnS[bi+1] = sqa; lnS[bi+2] = sub; lnS[bi+3] = sqb;
    }
    __syncthreads();
    {
        int oi = ((pair*2 + (1 - h))*8 + q)*4;
        sua += lnS[oi]; sqa += lnS[oi+1]; sub += lnS[oi+2]; sqb += lnS[oi+3];
    }
    float mua = sua * (1.f/128.f);
    float mub = sub * (1.f/128.f);
    float inva = rsqrtf(sqa*(1.f/128.f) - mua*mua + LN_EPS);
    float invb = rsqrtf(sqb*(1.f/128.f) - mub*mub + LN_EPS);

    float* outa = out + ((size_t)q*NN + na)*H;
    float* outb = out + ((size_t)q*NN + nb)*H;
#pragma unroll
    for (int nt = 0; nt < 8; nt++) {
        int c = col0 + nt*8;
        float2 lg = __ldg((const float2*)(ln_g + c));
        float2 lb = __ldg((const float2*)(ln_b + c));
        float2 oa = make_float2((oacc[nt][0] - mua)*inva*lg.x + lb.x,
                                (oacc[nt][1] - mua)*inva*lg.y + lb.y);
        float2 ob = make_float2((oacc[nt][2] - mub)*invb*lg.x + lb.x,
                                (oacc[nt][3] - mub)*invb*lg.y + lb.y);
        *(float2*)(outa + c) = oa;
        *(float2*)(outb + c) = ob;
    }
}

extern "C" void kernel_launch(void* const* d_in, const int* in_sizes, int n_in,
                              void* d_out, int out_size) {
    (void)in_sizes; (void)n_in; (void)out_size;
    const float* inter     = (const float*)d_in[0];
    const float* x         = (const float*)d_in[1];
    const float* proj_w    = (const float*)d_in[2];
    const float* proj_b    = (const float*)d_in[3];
    const float* q_w       = (const float*)d_in[4];
    const float* k_w       = (const float*)d_in[5];
    const float* v_w       = (const float*)d_in[6];
    const float* fc_w      = (const float*)d_in[7];
    const float* fc_b      = (const float*)d_in[8];
    const float* res_w     = (const float*)d_in[9];
    const float* res_b     = (const float*)d_in[10];
    const float* res_alpha = (const float*)d_in[11];
    const float* ln_g      = (const float*)d_in[12];
    const float* ln_b      = (const float*)d_in[13];
    float* out = (float*)d_out;

    const int smem = (8192 + 1024 + 256) * 4;   // 37888 B
    cudaFuncSetAttribute(htgnn_main, cudaFuncAttributeMaxDynamicSharedMemorySize,
                         smem);

    prep0_kernel<<<T, H>>>(proj_b);
    prep1_kernel<<<H, H>>>(proj_w, q_w, k_w, v_w, res_w);
    prep2_kernel<<<H, H>>>(fc_w);
    htgnn_main<<<NN/8, 256, smem>>>(inter, x, fc_b, res_b, res_alpha,
                                    ln_g, ln_b, out);
}

// round 7
// speedup vs baseline: 1.2117x; 1.2117x over previous
#include <cuda_runtime.h>
#include <cuda_fp16.h>
#include <math.h>
#include <stdint.h>

#define T 8
#define NN 100000
#define H 128
#define NIN 64
#define LN_EPS 1e-5f
#define WSCALE 64.f
#define WSCALE_INV 0.015625f

// ---------------- folded weights in mma-B-fragment layout (hi-only) --------
// slot idx = ((nt*KT+kt)*32+lane)*4 + grp*2 + p   (uint2 per lane-slot)
// nt=n/8, kt=k/16, lane=((n&7)<<2)|((k>>1)&3), grp=(k>>3)&1, p=k&1
__device__ __align__(8) __half g_wgF[17*8*32*4];   // [M | u^T] : 17 n-tiles
__device__ __align__(8) __half g_wvF[16*8*32*4];
__device__ __align__(8) __half g_wrF[16*4*32*4];
__device__ float g_wqP[H*H], g_wkP[H*H];           // plain folded Wq', Wk' [c][j]
__device__ float g_cq[T*H], g_ck[T*H], g_cv[T*H];  // [t][c]
__device__ float g_vv[T*H];                        // v_t[i] = sum_c cq[t,c] Wk'[c,i]
__device__ float g_cts[T*T];                       // c[t][s]
__device__ float g_hb[T*H];
__device__ float g_tmpVP[H*H];
__device__ float g_cvt[T*H];

template<int KT>
__device__ __forceinline__ void writeFrag(__half* wf, int n, int k, float w) {
    int nt = n >> 3, kt = k >> 4;
    int lane = ((n & 7) << 2) | ((k >> 1) & 3);
    int grp = (k >> 3) & 1, p = k & 1;
    wf[((nt*KT + kt)*32 + lane)*4 + grp*2 + p] = __float2half_rn(WSCALE * w);
}

// ---------------- prep kernels ----------------
__global__ void prep0_kernel(const float* __restrict__ proj_b) {
    int t = blockIdx.x, m = threadIdx.x;
    int i2 = m & ~1;
    double div = exp((double)i2 * (-log(100000.0)) / (double)H);
    double arg = (double)(t + 1) * div;
    double pe = (m & 1) ? cos(arg) : sin(arg);
    g_hb[t*H + m] = proj_b[m] + (float)pe;
}

__global__ void prep1_kernel(const float* __restrict__ proj_w,
                             const float* __restrict__ q_w,
                             const float* __restrict__ k_w,
                             const float* __restrict__ v_w,
                             const float* __restrict__ res_w) {
    int c = blockIdx.x, j = threadIdx.x;
    float sq = 0.f, sk = 0.f, sv = 0.f;
    for (int m = 0; m < H; m++) {
        float p = proj_w[m*H + j];
        sq = fmaf(q_w[c*H + m], p, sq);
        sk = fmaf(k_w[c*H + m], p, sk);
        sv = fmaf(v_w[c*H + m], p, sv);
    }
    g_wqP[c*H + j] = sq;
    g_wkP[c*H + j] = sk;
    g_tmpVP[c*H + j] = sv;
    if (j < NIN) writeFrag<4>(g_wrF, c, j, res_w[c*NIN + j]);
    if (j < T) {
        float a = 0.f, b = 0.f, vv = 0.f;
        for (int m = 0; m < H; m++) {
            float hb = g_hb[j*H + m];
            a  = fmaf(q_w[c*H + m], hb, a);
            b  = fmaf(k_w[c*H + m], hb, b);
            vv = fmaf(v_w[c*H + m], hb, vv);
        }
        g_cq[j*H + c] = a;
        g_ck[j*H + c] = b;
        g_cvt[j*H + c] = vv;
    }
}

__global__ void prep2_kernel(const float* __restrict__ fc_w) {
    int c = blockIdx.x, j = threadIdx.x;
    float s = 0.f;
    for (int m = 0; m < H; m++) s = fmaf(fc_w[c*H + m], g_tmpVP[m*H + j], s);
    writeFrag<8>(g_wvF, c, j, s);
    if (j < T) {
        float s2 = 0.f;
        for (int m = 0; m < H; m++) s2 = fmaf(fc_w[c*H + m], g_cvt[j*H + m], s2);
        g_cv[j*H + c] = s2;
    }
}

// M = Wq'^T Wk' ; u_s = Wq'^T ck_s ; vv_t = Wk'^T cq_t ; c_ts
__global__ void prep3_kernel() {
    int i = blockIdx.x, j = threadIdx.x;
    float m = 0.f;
    for (int c = 0; c < H; c++) m = fmaf(g_wqP[c*H + j], g_wkP[c*H + i], m);
    writeFrag<8>(g_wgF, i, j, m);     // B[n=i][k=j] = M[j][i]
    if (i < T) {
        float u = 0.f;
        for (int c = 0; c < H; c++) u = fmaf(g_wqP[c*H + j], g_ck[i*H + c], u);
        writeFrag<8>(g_wgF, 128 + i, j, u);   // Gu tile: n = 128+s
    }
    if (j < T) {
        float vv = 0.f;
        for (int c = 0; c < H; c++) vv = fmaf(g_cq[j*H + c], g_wkP[c*H + i], vv);
        g_vv[j*H + i] = vv;
    }
    if (i == 0 && j < T*T) {
        int t = j >> 3, s = j & 7;
        float cc = 0.f;
        for (int c = 0; c < H; c++) cc = fmaf(g_cq[t*H + c], g_ck[s*H + c], cc);
        g_cts[j] = cc;
    }
}

// ---------------- mma helpers ----------------
__device__ __forceinline__ void mma16816(float* c, const uint32_t* a,
                                         uint32_t b0, uint32_t b1) {
    asm volatile(
        "mma.sync.aligned.m16n8k16.row.col.f32.f16.f16.f32 "
        "{%0,%1,%2,%3},{%4,%5,%6,%7},{%8,%9},{%0,%1,%2,%3};\n"
        : "+f"(c[0]), "+f"(c[1]), "+f"(c[2]), "+f"(c[3])
        : "r"(a[0]), "r"(a[1]), "r"(a[2]), "r"(a[3]), "r"(b0), "r"(b1));
}

__device__ __forceinline__ uint32_t pack2(__half a, __half b) {
    __half2 t = __halves2half2(a, b);
    return *reinterpret_cast<uint32_t*>(&t);
}

__device__ __forceinline__ void mk_afrag(const float* aW, int kt, int lane,
                                         uint32_t* ahi, uint32_t* alo) {
#pragma unroll
    for (int p = 0; p < 4; p++) {
        float2 v = *(const float2*)(aW + (kt*4 + p)*64 + lane*2);
        __half hx = __float2half_rn(v.x), hy = __float2half_rn(v.y);
        ahi[p] = pack2(hx, hy);
        alo[p] = pack2(__float2half_rn(v.x - __half2float(hx)),
                       __float2half_rn(v.y - __half2float(hy)));
    }
}

// warp GEMM: 16 rows x NT*8 cols, K=KT*16, 2-pass (Ahi*W + Alo*W), fp32 accum
template<int KT, int NT>
__device__ __forceinline__ void wgemm(float acc[NT][4], const float* aW,
                                      const __half* wf, int lane) {
    const uint2* w2 = (const uint2*)wf;
#pragma unroll
    for (int kt = 0; kt < KT; kt++) {
        uint32_t ahi[4], alo[4];
        mk_afrag(aW, kt, lane, ahi, alo);
        uint2 b[NT];
#pragma unroll
        for (int nt = 0; nt < NT; nt++) {
            b[nt] = __ldg(&w2[(nt*KT + kt)*32 + lane]);
            mma16816(acc[nt], ahi, b[nt].x, b[nt].y);
        }
#pragma unroll
        for (int nt = 0; nt < NT; nt++)
            mma16816(acc[nt], alo, b[nt].x, b[nt].y);
    }
}

// ---------------- main kernel: 16 nodes/CTA, 8 warps, warp = 2 nodes -------
__global__ void __launch_bounds__(256, 1) htgnn_main(
    const float* __restrict__ inter, const float* __restrict__ x,
    const float* __restrict__ fc_b, const float* __restrict__ res_b,
    const float* __restrict__ res_alpha, const float* __restrict__ ln_g,
    const float* __restrict__ ln_b, float* __restrict__ out)
{
    extern __shared__ __align__(16) float aS[];   // 8KB per warp, warp-private
    const int tid = threadIdx.x;
    const int w = tid >> 5, lane = tid & 31;
    const int q = lane >> 2, j = lane & 3;
    const int node0 = blockIdx.x * 16;
    const int na = node0 + 2*w, nb = na + 1;
    float* aW = aS + w*2048;
    const unsigned FULL = 0xffffffffu;

    // ---- stage A (inter) frags ----
#pragma unroll
    for (int kt = 0; kt < 8; kt++)
#pragma unroll
        for (int p = 0; p < 4; p++) {
            int node = (p & 1) ? nb : na;
            int k = kt*16 + ((p >> 1) & 1)*8 + j*2;
            *(float2*)(aW + (kt*4 + p)*64 + lane*2) =
                *(const float2*)(inter + ((size_t)q*NN + node)*H + k);
        }
    __syncwarp();

    // ---- G = A @ [M | u^T]  (replaces Q and K GEMMs) ----
    float gacc[17][4] = {};
    wgemm<8, 17>(gacc, aW, g_wgF, lane);
    // scale; add v_t to the M-part columns
#pragma unroll
    for (int nt = 0; nt < 16; nt++) {
        float2 b = __ldg((const float2*)(g_vv + q*H + nt*8 + j*2));
        gacc[nt][0] = gacc[nt][0]*WSCALE_INV + b.x;
        gacc[nt][1] = gacc[nt][1]*WSCALE_INV + b.y;
        gacc[nt][2] = gacc[nt][2]*WSCALE_INV + b.x;
        gacc[nt][3] = gacc[nt][3]*WSCALE_INV + b.y;
    }
#pragma unroll
    for (int e = 0; e < 4; e++) gacc[16][e] *= WSCALE_INV;

    // ---- scores: d[t,s] = (G_t+v_t)·A_s (LDS broadcast) + Gu + c_ts ----
    float sa[8], sb[8];
#pragma unroll
    for (int s = 0; s < 8; s++) { sa[s] = 0.f; sb[s] = 0.f; }
#pragma unroll
    for (int nt = 0; nt < 16; nt++) {
        int kt = nt >> 1, grp = nt & 1;
        const float* baseA = aW + (kt*4 + 2*grp)*64;
        const float* baseB = baseA + 64;
#pragma unroll
        for (int s = 0; s < 8; s++) {
            float2 va = *(const float2*)(baseA + ((s << 2) | j)*2);
            float2 vb = *(const float2*)(baseB + ((s << 2) | j)*2);
            sa[s] = fmaf(gacc[nt][0], va.x, sa[s]);
            sa[s] = fmaf(gacc[nt][1], va.y, sa[s]);
            sb[s] = fmaf(gacc[nt][2], vb.x, sb[s]);
            sb[s] = fmaf(gacc[nt][3], vb.y, sb[s]);
        }
    }
#pragma unroll
    for (int s = 0; s < 8; s++) {
        sa[s] += __shfl_xor_sync(FULL, sa[s], 1);
        sa[s] += __shfl_xor_sync(FULL, sa[s], 2);
        sb[s] += __shfl_xor_sync(FULL, sb[s], 1);
        sb[s] += __shfl_xor_sync(FULL, sb[s], 2);
        int src = (q << 2) | (s >> 1);
        float gua = __shfl_sync(FULL, (s & 1) ? gacc[16][1] : gacc[16][0], src);
        float gub = __shfl_sync(FULL, (s & 1) ? gacc[16][3] : gacc[16][2], src);
        float cc = __ldg(&g_cts[q*8 + s]);
        sa[s] += gua + cc;
        sb[s] += gub + cc;
    }

    // ---- softmax ----
    float pa[8], pb[8];
    {
        float ma = sa[0], mb = sb[0];
#pragma unroll
        for (int s = 1; s < 8; s++) { ma = fmaxf(ma, sa[s]); mb = fmaxf(mb, sb[s]); }
        float za = 0.f, zb = 0.f;
#pragma unroll
        for (int s = 0; s < 8; s++) {
            pa[s] = expf(sa[s] - ma); za += pa[s];
            pb[s] = expf(sb[s] - mb); zb += pb[s];
        }
        float ia = 1.f/za, ib = 1.f/zb;
#pragma unroll
        for (int s = 0; s < 8; s++) { pa[s] *= ia; pb[s] *= ib; }
    }

    // ---- V (fc folded) ----
    float vacc[16][4] = {};
    wgemm<8, 16>(vacc, aW, g_wvF, lane);
#pragma unroll
    for (int nt = 0; nt < 16; nt++) {
        float2 b = __ldg((const float2*)(g_cv + q*H + nt*8 + j*2));
        vacc[nt][0] = vacc[nt][0]*WSCALE_INV + b.x;
        vacc[nt][1] = vacc[nt][1]*WSCALE_INV + b.y;
        vacc[nt][2] = vacc[nt][2]*WSCALE_INV + b.x;
        vacc[nt][3] = vacc[nt][3]*WSCALE_INV + b.y;
    }

    // ---- O = S @ V (warp-local shfl; row s lives in lanes (s<<2)|j) ----
    float oacc[16][4] = {};
#pragma unroll
    for (int s = 0; s < 8; s++) {
        int src = (s << 2) | j;
        float wa = pa[s], wb = pb[s];
#pragma unroll
        for (int nt = 0; nt < 16; nt++) {
            oacc[nt][0] = fmaf(wa, __shfl_sync(FULL, vacc[nt][0], src), oacc[nt][0]);
            oacc[nt][1] = fmaf(wa, __shfl_sync(FULL, vacc[nt][1], src), oacc[nt][1]);
            oacc[nt][2] = fmaf(wb, __shfl_sync(FULL, vacc[nt][2], src), oacc[nt][2]);
            oacc[nt][3] = fmaf(wb, __shfl_sync(FULL, vacc[nt][3], src), oacc[nt][3]);
        }
    }

    // ---- stage x frags (overwrites aW; warp-private) + res GEMM ----
    __syncwarp();
#pragma unroll
    for (int kt = 0; kt < 4; kt++)
#pragma unroll
        for (int p = 0; p < 4; p++) {
            int node = (p & 1) ? nb : na;
            int k = kt*16 + ((p >> 1) & 1)*8 + j*2;
            *(float2*)(aW + (kt*4 + p)*64 + lane*2) =
                *(const float2*)(x + ((size_t)q*NN + node)*NIN + k);
        }
    __syncwarp();
    float racc[16][4] = {};
    wgemm<4, 16>(racc, aW, g_wrF, lane);

    // ---- epilogue: relu/gate/LN/store ----
    float alpha = 1.f / (1.f + expf(-__ldg(res_alpha)));
    float beta = 1.f - alpha;
    float sua = 0.f, sqa = 0.f, sub = 0.f, sqb = 0.f;
#pragma unroll
    for (int nt = 0; nt < 16; nt++) {
        int c = nt*8 + j*2;
        float2 fb = __ldg((const float2*)(fc_b + c));
        float2 rb = __ldg((const float2*)(res_b + c));
        float v0 = fmaxf(oacc[nt][0] + fb.x, 0.f)*alpha +
                   (racc[nt][0]*WSCALE_INV + rb.x)*beta;
        float v1 = fmaxf(oacc[nt][1] + fb.y, 0.f)*alpha +
                   (racc[nt][1]*WSCALE_INV + rb.y)*beta;
        float v2 = fmaxf(oacc[nt][2] + fb.x, 0.f)*alpha +
                   (racc[nt][2]*WSCALE_INV + rb.x)*beta;
        float v3 = fmaxf(oacc[nt][3] + fb.y, 0.f)*alpha +
                   (racc[nt][3]*WSCALE_INV + rb.y)*beta;
        oacc[nt][0] = v0; oacc[nt][1] = v1; oacc[nt][2] = v2; oacc[nt][3] = v3;
        sua += v0 + v1; sqa += v0*v0 + v1*v1;
        sub += v2 + v3; sqb += v2*v2 + v3*v3;
    }
    sua += __shfl_xor_sync(FULL, sua, 1); sua += __shfl_xor_sync(FULL, sua, 2);
    sqa += __shfl_xor_sync(FULL, sqa, 1); sqa += __shfl_xor_sync(FULL, sqa, 2);
    sub += __shfl_xor_sync(FULL, sub, 1); sub += __shfl_xor_sync(FULL, sub, 2);
    sqb += __shfl_xor_sync(FULL, sqb, 1); sqb += __shfl_xor_sync(FULL, sqb, 2);
    float mua = sua * (1.f/128.f);
    float mub = sub * (1.f/128.f);
    float inva = rsqrtf(sqa*(1.f/128.f) - mua*mua + LN_EPS);
    float invb = rsqrtf(sqb*(1.f/128.f) - mub*mub + LN_EPS);

    float* outa = out + ((size_t)q*NN + na)*H;
    float* outb = out + ((size_t)q*NN + nb)*H;
#pragma unroll
    for (int nt = 0; nt < 16; nt++) {
        int c = nt*8 + j*2;
        float2 lg = __ldg((const float2*)(ln_g + c));
        float2 lb = __ldg((const float2*)(ln_b + c));
        float2 oa = make_float2((oacc[nt][0] - mua)*inva*lg.x + lb.x,
                                (oacc[nt][1] - mua)*inva*lg.y + lb.y);
        float2 ob = make_float2((oacc[nt][2] - mub)*invb*lg.x + lb.x,
                                (oacc[nt][3] - mub)*invb*lg.y + lb.y);
        *(float2*)(outa + c) = oa;
        *(float2*)(outb + c) = ob;
    }
}

extern "C" void kernel_launch(void* const* d_in, const int* in_sizes, int n_in,
                              void* d_out, int out_size) {
    (void)in_sizes; (void)n_in; (void)out_size;
    const float* inter     = (const float*)d_in[0];
    const float* x         = (const float*)d_in[1];
    const float* proj_w    = (const float*)d_in[2];
    const float* proj_b    = (const float*)d_in[3];
    const float* q_w       = (const float*)d_in[4];
    const float* k_w       = (const float*)d_in[5];
    const float* v_w       = (const float*)d_in[6];
    const float* fc_w      = (const float*)d_in[7];
    const float* fc_b      = (const float*)d_in[8];
    const float* res_w     = (const float*)d_in[9];
    const float* res_b     = (const float*)d_in[10];
    const float* res_alpha = (const float*)d_in[11];
    const float* ln_g      = (const float*)d_in[12];
    const float* ln_b      = (const float*)d_in[13];
    float* out = (float*)d_out;

    cudaFuncSetAttribute(htgnn_main, cudaFuncAttributeMaxDynamicSharedMemorySize,
                         65536);

    prep0_kernel<<<T, H>>>(proj_b);
    prep1_kernel<<<H, H>>>(proj_w, q_w, k_w, v_w, res_w);
    prep2_kernel<<<H, H>>>(fc_w);
    prep3_kernel<<<H, H>>>();
    htgnn_main<<<NN/16, 256, 65536>>>(inter, x, fc_b, res_b, res_alpha,
                                      ln_g, ln_b, out);
}

// round 8
// speedup vs baseline: 1.2575x; 1.0378x over previous
#include <cuda_runtime.h>
#include <cuda_fp16.h>
#include <math.h>
#include <stdint.h>

#define T 8
#define NN 100000
#define H 128
#define NIN 64
#define LN_EPS 1e-5f
#define WSCALE 64.f
#define WSCALE_INV 0.015625f

// ---------------- folded weights in mma-B-fragment layout (hi-only) --------
// slot idx = ((nt*KT+kt)*32+lane)*4 + grp*2 + p   (uint2 per lane-slot)
// nt=n/8, kt=k/16, lane=((n&7)<<2)|((k>>1)&3), grp=(k>>3)&1, p=k&1
__device__ __align__(8) __half g_wgF[17*8*32*4];   // [M | u^T] : 17 n-tiles
__device__ __align__(8) __half g_wvF[16*8*32*4];
__device__ __align__(8) __half g_wrF[16*4*32*4];
__device__ float g_wqP[H*H], g_wkP[H*H];           // plain folded Wq', Wk' [c][j]
__device__ float g_cq[T*H], g_ck[T*H], g_cv[T*H];  // [t][c]
__device__ float g_vv[T*H];                        // v_t[i] = sum_c cq[t,c] Wk'[c,i]
__device__ float g_cts[T*T];                       // c[t][s]
__device__ float g_hb[T*H];
__device__ float g_tmpVP[H*H];
__device__ float g_cvt[T*H];

template<int KT>
__device__ __forceinline__ void writeFrag(__half* wf, int n, int k, float w) {
    int nt = n >> 3, kt = k >> 4;
    int lane = ((n & 7) << 2) | ((k >> 1) & 3);
    int grp = (k >> 3) & 1, p = k & 1;
    wf[((nt*KT + kt)*32 + lane)*4 + grp*2 + p] = __float2half_rn(WSCALE * w);
}

// ---------------- prep kernels (4-way split accumulators, latency-hiding) --
__global__ void prep0_kernel(const float* __restrict__ proj_b) {
    int t = blockIdx.x, m = threadIdx.x;
    int i2 = m & ~1;
    double div = exp((double)i2 * (-log(100000.0)) / (double)H);
    double arg = (double)(t + 1) * div;
    double pe = (m & 1) ? cos(arg) : sin(arg);
    g_hb[t*H + m] = proj_b[m] + (float)pe;
}

__global__ void prep1_kernel(const float* __restrict__ proj_w,
                             const float* __restrict__ q_w,
                             const float* __restrict__ k_w,
                             const float* __restrict__ v_w,
                             const float* __restrict__ res_w) {
    int c = blockIdx.x, j = threadIdx.x;
    float sq0=0.f,sq1=0.f,sq2=0.f,sq3=0.f;
    float sk0=0.f,sk1=0.f,sk2=0.f,sk3=0.f;
    float sv0=0.f,sv1=0.f,sv2=0.f,sv3=0.f;
#pragma unroll 8
    for (int m = 0; m < H; m += 4) {
        float p0 = __ldg(&proj_w[(m+0)*H + j]);
        float p1 = __ldg(&proj_w[(m+1)*H + j]);
        float p2 = __ldg(&proj_w[(m+2)*H + j]);
        float p3 = __ldg(&proj_w[(m+3)*H + j]);
        sq0 = fmaf(__ldg(&q_w[c*H + m+0]), p0, sq0);
        sq1 = fmaf(__ldg(&q_w[c*H + m+1]), p1, sq1);
        sq2 = fmaf(__ldg(&q_w[c*H + m+2]), p2, sq2);
        sq3 = fmaf(__ldg(&q_w[c*H + m+3]), p3, sq3);
        sk0 = fmaf(__ldg(&k_w[c*H + m+0]), p0, sk0);
        sk1 = fmaf(__ldg(&k_w[c*H + m+1]), p1, sk1);
        sk2 = fmaf(__ldg(&k_w[c*H + m+2]), p2, sk2);
        sk3 = fmaf(__ldg(&k_w[c*H + m+3]), p3, sk3);
        sv0 = fmaf(__ldg(&v_w[c*H + m+0]), p0, sv0);
        sv1 = fmaf(__ldg(&v_w[c*H + m+1]), p1, sv1);
        sv2 = fmaf(__ldg(&v_w[c*H + m+2]), p2, sv2);
        sv3 = fmaf(__ldg(&v_w[c*H + m+3]), p3, sv3);
    }
    float sq = (sq0+sq1)+(sq2+sq3);
    float sk = (sk0+sk1)+(sk2+sk3);
    float sv = (sv0+sv1)+(sv2+sv3);
    g_wqP[c*H + j] = sq;
    g_wkP[c*H + j] = sk;
    g_tmpVP[c*H + j] = sv;
    if (j < NIN) writeFrag<4>(g_wrF, c, j, res_w[c*NIN + j]);
    if (j < T) {
        float a0=0.f,a1=0.f,b0=0.f,b1=0.f,v0=0.f,v1=0.f;
#pragma unroll 8
        for (int m = 0; m < H; m += 2) {
            float h0 = g_hb[j*H + m], h1 = g_hb[j*H + m+1];
            a0 = fmaf(__ldg(&q_w[c*H + m]),   h0, a0);
            a1 = fmaf(__ldg(&q_w[c*H + m+1]), h1, a1);
            b0 = fmaf(__ldg(&k_w[c*H + m]),   h0, b0);
            b1 = fmaf(__ldg(&k_w[c*H + m+1]), h1, b1);
            v0 = fmaf(__ldg(&v_w[c*H + m]),   h0, v0);
            v1 = fmaf(__ldg(&v_w[c*H + m+1]), h1, v1);
        }
        g_cq[j*H + c] = a0 + a1;
        g_ck[j*H + c] = b0 + b1;
        g_cvt[j*H + c] = v0 + v1;
    }
}

__global__ void prep2_kernel(const float* __restrict__ fc_w) {
    int c = blockIdx.x, j = threadIdx.x;
    float s0=0.f,s1=0.f,s2=0.f,s3=0.f;
#pragma unroll 8
    for (int m = 0; m < H; m += 4) {
        s0 = fmaf(__ldg(&fc_w[c*H + m+0]), g_tmpVP[(m+0)*H + j], s0);
        s1 = fmaf(__ldg(&fc_w[c*H + m+1]), g_tmpVP[(m+1)*H + j], s1);
        s2 = fmaf(__ldg(&fc_w[c*H + m+2]), g_tmpVP[(m+2)*H + j], s2);
        s3 = fmaf(__ldg(&fc_w[c*H + m+3]), g_tmpVP[(m+3)*H + j], s3);
    }
    writeFrag<8>(g_wvF, c, j, (s0+s1)+(s2+s3));
    if (j < T) {
        float t0=0.f,t1=0.f;
#pragma unroll 8
        for (int m = 0; m < H; m += 2) {
            t0 = fmaf(__ldg(&fc_w[c*H + m]),   g_cvt[j*H + m],   t0);
            t1 = fmaf(__ldg(&fc_w[c*H + m+1]), g_cvt[j*H + m+1], t1);
        }
        g_cv[j*H + c] = t0 + t1;
    }
}

// M = Wq'^T Wk' ; u_s = Wq'^T ck_s ; vv_t = Wk'^T cq_t ; c_ts
__global__ void prep3_kernel() {
    int i = blockIdx.x, j = threadIdx.x;
    float m0=0.f,m1=0.f,m2=0.f,m3=0.f;
#pragma unroll 8
    for (int c = 0; c < H; c += 4) {
        m0 = fmaf(g_wqP[(c+0)*H + j], g_wkP[(c+0)*H + i], m0);
        m1 = fmaf(g_wqP[(c+1)*H + j], g_wkP[(c+1)*H + i], m1);
        m2 = fmaf(g_wqP[(c+2)*H + j], g_wkP[(c+2)*H + i], m2);
        m3 = fmaf(g_wqP[(c+3)*H + j], g_wkP[(c+3)*H + i], m3);
    }
    writeFrag<8>(g_wgF, i, j, (m0+m1)+(m2+m3));   // B[n=i][k=j] = M[j][i]
    if (i < T) {
        float u0=0.f,u1=0.f;
#pragma unroll 8
        for (int c = 0; c < H; c += 2) {
            u0 = fmaf(g_wqP[c*H + j],     g_ck[i*H + c],   u0);
            u1 = fmaf(g_wqP[(c+1)*H + j], g_ck[i*H + c+1], u1);
        }
        writeFrag<8>(g_wgF, 128 + i, j, u0 + u1);  // Gu tile: n = 128+s
    }
    if (j < T) {
        float v0=0.f,v1=0.f;
#pragma unroll 8
        for (int c = 0; c < H; c += 2) {
            v0 = fmaf(g_cq[j*H + c],   g_wkP[c*H + i],     v0);
            v1 = fmaf(g_cq[j*H + c+1], g_wkP[(c+1)*H + i], v1);
        }
        g_vv[j*H + i] = v0 + v1;
    }
    if (i == 0 && j < T*T) {
        int t = j >> 3, s = j & 7;
        float c0=0.f,c1=0.f;
#pragma unroll 8
        for (int c = 0; c < H; c += 2) {
            c0 = fmaf(g_cq[t*H + c],   g_ck[s*H + c],   c0);
            c1 = fmaf(g_cq[t*H + c+1], g_ck[s*H + c+1], c1);
        }
        g_cts[j] = c0 + c1;
    }
}

// ---------------- mma helpers ----------------
__device__ __forceinline__ void mma16816(float* c, const uint32_t* a,
                                         uint32_t b0, uint32_t b1) {
    asm volatile(
        "mma.sync.aligned.m16n8k16.row.col.f32.f16.f16.f32 "
        "{%0,%1,%2,%3},{%4,%5,%6,%7},{%8,%9},{%0,%1,%2,%3};\n"
        : "+f"(c[0]), "+f"(c[1]), "+f"(c[2]), "+f"(c[3])
        : "r"(a[0]), "r"(a[1]), "r"(a[2]), "r"(a[3]), "r"(b0), "r"(b1));
}

__device__ __forceinline__ uint32_t pack2(__half a, __half b) {
    __half2 t = __halves2half2(a, b);
    return *reinterpret_cast<uint32_t*>(&t);
}

// warp GEMM: 16 rows x NT*8 cols, K=KT*16, PASSES in {1,2}; fp32 accum.
// PASSES==2 adds the A-residual (lo) pass for near-fp32 activation precision.
template<int KT, int NT, int PASSES>
__device__ __forceinline__ void wgemm(float acc[NT][4], const float* aW,
                                      const __half* wf, int lane) {
    const uint2* w2 = (const uint2*)wf;
#pragma unroll
    for (int kt = 0; kt < KT; kt++) {
        uint32_t ahi[4], alo[4];
#pragma unroll
        for (int p = 0; p < 4; p++) {
            float2 v = *(const float2*)(aW + (kt*4 + p)*64 + lane*2);
            __half hx = __float2half_rn(v.x), hy = __float2half_rn(v.y);
            ahi[p] = pack2(hx, hy);
            if (PASSES == 2)
                alo[p] = pack2(__float2half_rn(v.x - __half2float(hx)),
                               __float2half_rn(v.y - __half2float(hy)));
        }
        uint2 b[NT];
#pragma unroll
        for (int nt = 0; nt < NT; nt++) {
            b[nt] = __ldg(&w2[(nt*KT + kt)*32 + lane]);
            mma16816(acc[nt], ahi, b[nt].x, b[nt].y);
        }
        if (PASSES == 2) {
#pragma unroll
            for (int nt = 0; nt < NT; nt++)
                mma16816(acc[nt], alo, b[nt].x, b[nt].y);
        }
    }
}

// ---------------- main kernel: 16 nodes/CTA, 8 warps, warp = 2 nodes -------
__global__ void __launch_bounds__(256, 1) htgnn_main(
    const float* __restrict__ inter, const float* __restrict__ x,
    const float* __restrict__ fc_b, const float* __restrict__ res_b,
    const float* __restrict__ res_alpha, const float* __restrict__ ln_g,
    const float* __restrict__ ln_b, float* __restrict__ out)
{
    extern __shared__ __align__(16) float aS[];   // 8KB per warp, warp-private
    const int tid = threadIdx.x;
    const int w = tid >> 5, lane = tid & 31;
    const int q = lane >> 2, j = lane & 3;
    const int node0 = blockIdx.x * 16;
    const int na = node0 + 2*w, nb = na + 1;
    float* aW = aS + w*2048;
    const unsigned FULL = 0xffffffffu;

    // ---- stage A (inter) frags ----
#pragma unroll
    for (int kt = 0; kt < 8; kt++)
#pragma unroll
        for (int p = 0; p < 4; p++) {
            int node = (p & 1) ? nb : na;
            int k = kt*16 + ((p >> 1) & 1)*8 + j*2;
            *(float2*)(aW + (kt*4 + p)*64 + lane*2) =
                *(const float2*)(inter + ((size_t)q*NN + node)*H + k);
        }
    __syncwarp();

    // ---- G = A @ [M | u^T]  (replaces Q and K GEMMs); 2-pass for precision --
    float gacc[17][4] = {};
    wgemm<8, 17, 2>(gacc, aW, g_wgF, lane);
#pragma unroll
    for (int nt = 0; nt < 16; nt++) {
        float2 b = __ldg((const float2*)(g_vv + q*H + nt*8 + j*2));
        gacc[nt][0] = gacc[nt][0]*WSCALE_INV + b.x;
        gacc[nt][1] = gacc[nt][1]*WSCALE_INV + b.y;
        gacc[nt][2] = gacc[nt][2]*WSCALE_INV + b.x;
        gacc[nt][3] = gacc[nt][3]*WSCALE_INV + b.y;
    }
#pragma unroll
    for (int e = 0; e < 4; e++) gacc[16][e] *= WSCALE_INV;

    // ---- scores: d[t,s] = (G_t+v_t)·A_s (LDS broadcast) + Gu + c_ts ----
    float sa[8], sb[8];
#pragma unroll
    for (int s = 0; s < 8; s++) { sa[s] = 0.f; sb[s] = 0.f; }
#pragma unroll
    for (int nt = 0; nt < 16; nt++) {
        int kt = nt >> 1, grp = nt & 1;
        const float* baseA = aW + (kt*4 + 2*grp)*64;
        const float* baseB = baseA + 64;
#pragma unroll
        for (int s = 0; s < 8; s++) {
            float2 va = *(const float2*)(baseA + ((s << 2) | j)*2);
            float2 vb = *(const float2*)(baseB + ((s << 2) | j)*2);
            sa[s] = fmaf(gacc[nt][0], va.x, sa[s]);
            sa[s] = fmaf(gacc[nt][1], va.y, sa[s]);
            sb[s] = fmaf(gacc[nt][2], vb.x, sb[s]);
            sb[s] = fmaf(gacc[nt][3], vb.y, sb[s]);
        }
    }
#pragma unroll
    for (int s = 0; s < 8; s++) {
        sa[s] += __shfl_xor_sync(FULL, sa[s], 1);
        sa[s] += __shfl_xor_sync(FULL, sa[s], 2);
        sb[s] += __shfl_xor_sync(FULL, sb[s], 1);
        sb[s] += __shfl_xor_sync(FULL, sb[s], 2);
        int src = (q << 2) | (s >> 1);
        float gua = __shfl_sync(FULL, (s & 1) ? gacc[16][1] : gacc[16][0], src);
        float gub = __shfl_sync(FULL, (s & 1) ? gacc[16][3] : gacc[16][2], src);
        float cc = __ldg(&g_cts[q*8 + s]);
        sa[s] += gua + cc;
        sb[s] += gub + cc;
    }

    // ---- softmax ----
    float pa[8], pb[8];
    {
        float ma = sa[0], mb = sb[0];
#pragma unroll
        for (int s = 1; s < 8; s++) { ma = fmaxf(ma, sa[s]); mb = fmaxf(mb, sb[s]); }
        float za = 0.f, zb = 0.f;
#pragma unroll
        for (int s = 0; s < 8; s++) {
            pa[s] = expf(sa[s] - ma); za += pa[s];
            pb[s] = expf(sb[s] - mb); zb += pb[s];
        }
        float ia = 1.f/za, ib = 1.f/zb;
#pragma unroll
        for (int s = 0; s < 8; s++) { pa[s] *= ia; pb[s] *= ib; }
    }

    // ---- V (fc folded); single-pass (error damped by softmax-avg + LN) ----
    float vacc[16][4] = {};
    wgemm<8, 16, 1>(vacc, aW, g_wvF, lane);
#pragma unroll
    for (int nt = 0; nt < 16; nt++) {
        float2 b = __ldg((const float2*)(g_cv + q*H + nt*8 + j*2));
        vacc[nt][0] = vacc[nt][0]*WSCALE_INV + b.x;
        vacc[nt][1] = vacc[nt][1]*WSCALE_INV + b.y;
        vacc[nt][2] = vacc[nt][2]*WSCALE_INV + b.x;
        vacc[nt][3] = vacc[nt][3]*WSCALE_INV + b.y;
    }

    // ---- O = S @ V (warp-local shfl; row s lives in lanes (s<<2)|j) ----
    float oacc[16][4] = {};
#pragma unroll
    for (int s = 0; s < 8; s++) {
        int src = (s << 2) | j;
        float wa = pa[s], wb = pb[s];
#pragma unroll
        for (int nt = 0; nt < 16; nt++) {
            oacc[nt][0] = fmaf(wa, __shfl_sync(FULL, vacc[nt][0], src), oacc[nt][0]);
            oacc[nt][1] = fmaf(wa, __shfl_sync(FULL, vacc[nt][1], src), oacc[nt][1]);
            oacc[nt][2] = fmaf(wb, __shfl_sync(FULL, vacc[nt][2], src), oacc[nt][2]);
            oacc[nt][3] = fmaf(wb, __shfl_sync(FULL, vacc[nt][3], src), oacc[nt][3]);
        }
    }

    // ---- stage x frags (overwrites aW; warp-private) + res GEMM (1-pass) ----
    __syncwarp();
#pragma unroll
    for (int kt = 0; kt < 4; kt++)
#pragma unroll
        for (int p = 0; p < 4; p++) {
            int node = (p & 1) ? nb : na;
            int k = kt*16 + ((p >> 1) & 1)*8 + j*2;
            *(float2*)(aW + (kt*4 + p)*64 + lane*2) =
                *(const float2*)(x + ((size_t)q*NN + node)*NIN + k);
        }
    __syncwarp();
    float racc[16][4] = {};
    wgemm<4, 16, 1>(racc, aW, g_wrF, lane);

    // ---- epilogue: relu/gate/LN/store ----
    float alpha = 1.f / (1.f + expf(-__ldg(res_alpha)));
    float beta = 1.f - alpha;
    float sua = 0.f, sqa = 0.f, sub = 0.f, sqb = 0.f;
#pragma unroll
    for (int nt = 0; nt < 16; nt++) {
        int c = nt*8 + j*2;
        float2 fb = __ldg((const float2*)(fc_b + c));
        float2 rb = __ldg((const float2*)(res_b + c));
        float v0 = fmaxf(oacc[nt][0] + fb.x, 0.f)*alpha +
                   (racc[nt][0]*WSCALE_INV + rb.x)*beta;
        float v1 = fmaxf(oacc[nt][1] + fb.y, 0.f)*alpha +
                   (racc[nt][1]*WSCALE_INV + rb.y)*beta;
        float v2 = fmaxf(oacc[nt][2] + fb.x, 0.f)*alpha +
                   (racc[nt][2]*WSCALE_INV + rb.x)*beta;
        float v3 = fmaxf(oacc[nt][3] + fb.y, 0.f)*alpha +
                   (racc[nt][3]*WSCALE_INV + rb.y)*beta;
        oacc[nt][0] = v0; oacc[nt][1] = v1; oacc[nt][2] = v2; oacc[nt][3] = v3;
        sua += v0 + v1; sqa += v0*v0 + v1*v1;
        sub += v2 + v3; sqb += v2*v2 + v3*v3;
    }
    sua += __shfl_xor_sync(FULL, sua, 1); sua += __shfl_xor_sync(FULL, sua, 2);
    sqa += __shfl_xor_sync(FULL, sqa, 1); sqa += __shfl_xor_sync(FULL, sqa, 2);
    sub += __shfl_xor_sync(FULL, sub, 1); sub += __shfl_xor_sync(FULL, sub, 2);
    sqb += __shfl_xor_sync(FULL, sqb, 1); sqb += __shfl_xor_sync(FULL, sqb, 2);
    float mua = sua * (1.f/128.f);
    float mub = sub * (1.f/128.f);
    float inva = rsqrtf(sqa*(1.f/128.f) - mua*mua + LN_EPS);
    float invb = rsqrtf(sqb*(1.f/128.f) - mub*mub + LN_EPS);

    float* outa = out + ((size_t)q*NN + na)*H;
    float* outb = out + ((size_t)q*NN + nb)*H;
#pragma unroll
    for (int nt = 0; nt < 16; nt++) {
        int c = nt*8 + j*2;
        float2 lg = __ldg((const float2*)(ln_g + c));
        float2 lb = __ldg((const float2*)(ln_b + c));
        float2 oa = make_float2((oacc[nt][0] - mua)*inva*lg.x + lb.x,
                                (oacc[nt][1] - mua)*inva*lg.y + lb.y);
        float2 ob = make_float2((oacc[nt][2] - mub)*invb*lg.x + lb.x,
                                (oacc[nt][3] - mub)*invb*lg.y + lb.y);
        *(float2*)(outa + c) = oa;
        *(float2*)(outb + c) = ob;
    }
}

extern "C" void kernel_launch(void* const* d_in, const int* in_sizes, int n_in,
                              void* d_out, int out_size) {
    (void)in_sizes; (void)n_in; (void)out_size;
    const float* inter     = (const float*)d_in[0];
    const float* x         = (const float*)d_in[1];
    const float* proj_w    = (const float*)d_in[2];
    const float* proj_b    = (const float*)d_in[3];
    const float* q_w       = (const float*)d_in[4];
    const float* k_w       = (const float*)d_in[5];
    const float* v_w       = (const float*)d_in[6];
    const float* fc_w      = (const float*)d_in[7];
    const float* fc_b      = (const float*)d_in[8];
    const float* res_w     = (const float*)d_in[9];
    const float* res_b     = (const float*)d_in[10];
    const float* res_alpha = (const float*)d_in[11];
    const float* ln_g      = (const float*)d_in[12];
    const float* ln_b      = (const float*)d_in[13];
    float* out = (float*)d_out;

    cudaFuncSetAttribute(htgnn_main, cudaFuncAttributeMaxDynamicSharedMemorySize,
                         65536);

    prep0_kernel<<<T, H>>>(proj_b);
    prep1_kernel<<<H, H>>>(proj_w, q_w, k_w, v_w, res_w);
    prep2_kernel<<<H, H>>>(fc_w);
    prep3_kernel<<<H, H>>>();
    htgnn_main<<<NN/16, 256, 65536>>>(inter, x, fc_b, res_b, res_alpha,
                                      ln_g, ln_b, out);
}

// round 9
// speedup vs baseline: 1.7113x; 1.3609x over previous
#include <cuda_runtime.h>
#include <cuda_fp16.h>
#include <math.h>
#include <stdint.h>

#define T 8
#define NN 100000
#define H 128
#define NIN 64
#define LN_EPS 1e-5f
#define WSCALE 64.f
#define WSCALE_INV 0.015625f

// ---------------- folded weights in mma-B-fragment layout (hi-only) --------
// slot idx = ((nt*KT+kt)*32+lane)*4 + grp*2 + p   (uint2 per lane-slot)
// nt=n/8, kt=k/16, lane=((n&7)<<2)|((k>>1)&3), grp=(k>>3)&1, p=k&1
__device__ __align__(8) __half g_wgF[17*8*32*4];   // [M | u^T] : 17 n-tiles
__device__ __align__(8) __half g_wvF[16*9*32*4];   // [Wv ; cv] : 9 k-tiles (aug)
__device__ __align__(8) __half g_wrF[16*4*32*4];
__device__ float g_wqP[H*H], g_wkP[H*H];           // plain folded Wq', Wk' [c][j]
__device__ float g_cq[T*H], g_ck[T*H];             // [t][c]
__device__ float g_vv[T*H];                        // v_t[i] = sum_c cq[t,c] Wk'[c,i]
__device__ float g_cts[T*T];                       // c[t][s]
__device__ float g_hb[T*H];
__device__ float g_tmpVP[H*H];
__device__ float g_cvt[T*H];

template<int KT>
__device__ __forceinline__ void writeFrag(__half* wf, int n, int k, float w) {
    int nt = n >> 3, kt = k >> 4;
    int lane = ((n & 7) << 2) | ((k >> 1) & 3);
    int grp = (k >> 3) & 1, p = k & 1;
    wf[((nt*KT + kt)*32 + lane)*4 + grp*2 + p] = __float2half_rn(WSCALE * w);
}

// ---------------- prep kernels: K-split-4 + SMEM reduce ----------------
__global__ void prep0_kernel(const float* __restrict__ proj_b) {
    int t = blockIdx.x, m = threadIdx.x;
    int i2 = m & ~1;
    double div = exp((double)i2 * (-log(100000.0)) / (double)H);
    double arg = (double)(t + 1) * div;
    double pe = (m & 1) ? cos(arg) : sin(arg);
    g_hb[t*H + m] = proj_b[m] + (float)pe;
}

__global__ void prep1_kernel(const float* __restrict__ proj_w,
                             const float* __restrict__ q_w,
                             const float* __restrict__ k_w,
                             const float* __restrict__ v_w,
                             const float* __restrict__ res_w) {
    __shared__ float red[12*128];
    int c = blockIdx.x, tid = threadIdx.x;
    int j = tid & 127, kq = tid >> 7;
    float sq = 0.f, sk = 0.f, sv = 0.f;
    int m0 = kq*32;
#pragma unroll 8
    for (int m = m0; m < m0 + 32; m++) {
        float p = __ldg(&proj_w[m*H + j]);
        sq = fmaf(__ldg(&q_w[c*H + m]), p, sq);
        sk = fmaf(__ldg(&k_w[c*H + m]), p, sk);
        sv = fmaf(__ldg(&v_w[c*H + m]), p, sv);
    }
    red[kq*128 + j] = sq;
    red[512 + kq*128 + j] = sk;
    red[1024 + kq*128 + j] = sv;
    __syncthreads();
    if (kq == 0) {
        sq = (red[j] + red[128+j]) + (red[256+j] + red[384+j]);
        sk = (red[512+j] + red[640+j]) + (red[768+j] + red[896+j]);
        sv = (red[1024+j] + red[1152+j]) + (red[1280+j] + red[1408+j]);
        g_wqP[c*H + j] = sq;
        g_wkP[c*H + j] = sk;
        g_tmpVP[c*H + j] = sv;
        if (j < NIN) writeFrag<4>(g_wrF, c, j, res_w[c*NIN + j]);
    } else if (kq == 1 && j < T) {
        float a0=0.f,a1=0.f,b0=0.f,b1=0.f,v0=0.f,v1=0.f;
#pragma unroll 8
        for (int m = 0; m < H; m += 2) {
            float h0 = g_hb[j*H + m], h1 = g_hb[j*H + m+1];
            a0 = fmaf(__ldg(&q_w[c*H + m]),   h0, a0);
            a1 = fmaf(__ldg(&q_w[c*H + m+1]), h1, a1);
            b0 = fmaf(__ldg(&k_w[c*H + m]),   h0, b0);
            b1 = fmaf(__ldg(&k_w[c*H + m+1]), h1, b1);
            v0 = fmaf(__ldg(&v_w[c*H + m]),   h0, v0);
            v1 = fmaf(__ldg(&v_w[c*H + m+1]), h1, v1);
        }
        g_cq[j*H + c] = a0 + a1;
        g_ck[j*H + c] = b0 + b1;
        g_cvt[j*H + c] = v0 + v1;
    }
}

__global__ void prep2_kernel(const float* __restrict__ fc_w) {
    __shared__ float red[4*128];
    int c = blockIdx.x, tid = threadIdx.x;
    int j = tid & 127, kq = tid >> 7;
    float s = 0.f;
    int m0 = kq*32;
#pragma unroll 8
    for (int m = m0; m < m0 + 32; m++)
        s = fmaf(__ldg(&fc_w[c*H + m]), g_tmpVP[m*H + j], s);
    red[kq*128 + j] = s;
    __syncthreads();
    if (kq == 0) {
        s = (red[j] + red[128+j]) + (red[256+j] + red[384+j]);
        writeFrag<9>(g_wvF, c, j, s);                 // Wv part (kt 0..7)
    } else if (kq == 1 && j < T) {
        float t0=0.f,t1=0.f;
#pragma unroll 8
        for (int m = 0; m < H; m += 2) {
            t0 = fmaf(__ldg(&fc_w[c*H + m]),   g_cvt[j*H + m],   t0);
            t1 = fmaf(__ldg(&fc_w[c*H + m+1]), g_cvt[j*H + m+1], t1);
        }
        writeFrag<9>(g_wvF, c, 128 + j, t0 + t1);     // cv row in aug kt=8
    }
}

// M = Wq'^T Wk' ; u_s = Wq'^T ck_s ; vv_t = Wk'^T cq_t ; c_ts
__global__ void prep3_kernel() {
    __shared__ float red[4*128];
    int i = blockIdx.x, tid = threadIdx.x;
    int j = tid & 127, kq = tid >> 7;
    float m = 0.f;
    int c0 = kq*32;
#pragma unroll 8
    for (int c = c0; c < c0 + 32; c++)
        m = fmaf(g_wqP[c*H + j], g_wkP[c*H + i], m);
    red[kq*128 + j] = m;
    __syncthreads();
    if (kq == 0) {
        m = (red[j] + red[128+j]) + (red[256+j] + red[384+j]);
        writeFrag<8>(g_wgF, i, j, m);                 // B[n=i][k=j] = M[j][i]
    } else if (kq == 1 && i < T) {
        float u0=0.f,u1=0.f;
#pragma unroll 8
        for (int c = 0; c < H; c += 2) {
            u0 = fmaf(g_wqP[c*H + j],     g_ck[i*H + c],   u0);
            u1 = fmaf(g_wqP[(c+1)*H + j], g_ck[i*H + c+1], u1);
        }
        writeFrag<8>(g_wgF, 128 + i, j, u0 + u1);     // Gu tile: n = 128+s
    } else if (kq == 2 && j < T) {
        float v0=0.f,v1=0.f;
#pragma unroll 8
        for (int c = 0; c < H; c += 2) {
            v0 = fmaf(g_cq[j*H + c],   g_wkP[c*H + i],     v0);
            v1 = fmaf(g_cq[j*H + c+1], g_wkP[(c+1)*H + i], v1);
        }
        g_vv[j*H + i] = v0 + v1;
    } else if (kq == 3 && i == 0 && j < T*T) {
        int t = j >> 3, s = j & 7;
        float c0f=0.f,c1f=0.f;
#pragma unroll 8
        for (int c = 0; c < H; c += 2) {
            c0f = fmaf(g_cq[t*H + c],   g_ck[s*H + c],   c0f);
            c1f = fmaf(g_cq[t*H + c+1], g_ck[s*H + c+1], c1f);
        }
        g_cts[j] = c0f + c1f;
    }
}

// ---------------- mma helpers ----------------
__device__ __forceinline__ void mma16816(float* c, const uint32_t* a,
                                         uint32_t b0, uint32_t b1) {
    asm volatile(
        "mma.sync.aligned.m16n8k16.row.col.f32.f16.f16.f32 "
        "{%0,%1,%2,%3},{%4,%5,%6,%7},{%8,%9},{%0,%1,%2,%3};\n"
        : "+f"(c[0]), "+f"(c[1]), "+f"(c[2]), "+f"(c[3])
        : "r"(a[0]), "r"(a[1]), "r"(a[2]), "r"(a[3]), "r"(b0), "r"(b1));
}
__device__ __forceinline__ void mma1688(float* c, uint32_t a0, uint32_t a1,
                                        uint32_t b0) {
    asm volatile(
        "mma.sync.aligned.m16n8k8.row.col.f32.f16.f16.f32 "
        "{%0,%1,%2,%3},{%4,%5},{%6},{%0,%1,%2,%3};\n"
        : "+f"(c[0]), "+f"(c[1]), "+f"(c[2]), "+f"(c[3])
        : "r"(a0), "r"(a1), "r"(b0));
}
__device__ __forceinline__ uint32_t pack2(__half a, __half b) {
    __half2 t = __halves2half2(a, b);
    return *reinterpret_cast<uint32_t*>(&t);
}
__device__ __forceinline__ uint32_t packf(float a, float b) {
    return pack2(__float2half_rn(a), __float2half_rn(b));
}

// warp GEMM: 16 rows x NT*8 cols, K=KT*16, PASSES in {1,2}; fp32 accum.
template<int KT, int NT, int PASSES>
__device__ __forceinline__ void wgemm(float acc[NT][4], const float* aW,
                                      const __half* wf, int lane) {
    const uint2* w2 = (const uint2*)wf;
#pragma unroll
    for (int kt = 0; kt < KT; kt++) {
        uint32_t ahi[4], alo[4];
#pragma unroll
        for (int p = 0; p < 4; p++) {
            float2 v = *(const float2*)(aW + (kt*4 + p)*64 + lane*2);
            __half hx = __float2half_rn(v.x), hy = __float2half_rn(v.y);
            ahi[p] = pack2(hx, hy);
            if (PASSES == 2)
                alo[p] = packf(v.x - __half2float(hx), v.y - __half2float(hy));
        }
        uint2 b[NT];
#pragma unroll
        for (int nt = 0; nt < NT; nt++) {
            b[nt] = __ldg(&w2[(nt*KT + kt)*32 + lane]);
            mma16816(acc[nt], ahi, b[nt].x, b[nt].y);
        }
        if (PASSES == 2) {
#pragma unroll
            for (int nt = 0; nt < NT; nt++)
                mma16816(acc[nt], alo, b[nt].x, b[nt].y);
        }
    }
}

// ---------------- main kernel: 16 nodes/CTA, 8 warps, warp = 2 nodes -------
__global__ void __launch_bounds__(256, 1) htgnn_main(
    const float* __restrict__ inter, const float* __restrict__ x,
    const float* __restrict__ fc_b, const float* __restrict__ res_b,
    const float* __restrict__ res_alpha, const float* __restrict__ ln_g,
    const float* __restrict__ ln_b, float* __restrict__ out)
{
    extern __shared__ __align__(16) float aS[];   // 8KB per warp, warp-private
    const int tid = threadIdx.x;
    const int w = tid >> 5, lane = tid & 31;
    const int q = lane >> 2, j = lane & 3;
    const int node0 = blockIdx.x * 16;
    const int na = node0 + 2*w, nb = na + 1;
    float* aW = aS + w*2048;
    const unsigned FULL = 0xffffffffu;

    // ---- stage A (inter) frags ----
#pragma unroll
    for (int kt = 0; kt < 8; kt++)
#pragma unroll
        for (int p = 0; p < 4; p++) {
            int node = (p & 1) ? nb : na;
            int k = kt*16 + ((p >> 1) & 1)*8 + j*2;
            *(float2*)(aW + (kt*4 + p)*64 + lane*2) =
                *(const float2*)(inter + ((size_t)q*NN + node)*H + k);
        }
    __syncwarp();

    // ---- G = A @ [M | u^T]  (2-pass) ----
    float gacc[17][4] = {};
    wgemm<8, 17, 2>(gacc, aW, g_wgF, lane);
#pragma unroll
    for (int nt = 0; nt < 16; nt++) {
        float2 b = __ldg((const float2*)(g_vv + q*H + nt*8 + j*2));
        gacc[nt][0] = gacc[nt][0]*WSCALE_INV + b.x;
        gacc[nt][1] = gacc[nt][1]*WSCALE_INV + b.y;
        gacc[nt][2] = gacc[nt][2]*WSCALE_INV + b.x;
        gacc[nt][3] = gacc[nt][3]*WSCALE_INV + b.y;
    }
#pragma unroll
    for (int e = 0; e < 4; e++) gacc[16][e] *= WSCALE_INV;

    // ---- scores via MMA: d = Ghat @ A^T, 3-pass (hh + lo_G·h + h·lo_A) ----
    float dA[4] = {}, dB[4] = {};
#pragma unroll
    for (int kt = 0; kt < 8; kt++) {
        uint32_t gh[4], gl[4];
#pragma unroll
        for (int h2 = 0; h2 < 2; h2++) {
            const float* g0 = gacc[2*kt + h2];
            __half ha = __float2half_rn(g0[0]), hb = __float2half_rn(g0[1]);
            __half hc = __float2half_rn(g0[2]), hd = __float2half_rn(g0[3]);
            gh[h2*2 + 0] = pack2(ha, hb);       // rows 0-7  (a0 / a2)
            gh[h2*2 + 1] = pack2(hc, hd);       // rows 8-15 (a1 / a3)
            gl[h2*2 + 0] = packf(g0[0]-__half2float(ha), g0[1]-__half2float(hb));
            gl[h2*2 + 1] = packf(g0[2]-__half2float(hc), g0[3]-__half2float(hd));
        }
        // a-frag order {a0,a1,a2,a3} = {gh[0],gh[1],gh[2],gh[3]} already
        uint32_t bh[4], bl[4];
#pragma unroll
        for (int p = 0; p < 4; p++) {
            float2 v = *(const float2*)(aW + (kt*4 + p)*64 + lane*2);
            __half hx = __float2half_rn(v.x), hy = __float2half_rn(v.y);
            bh[p] = pack2(hx, hy);
            bl[p] = packf(v.x - __half2float(hx), v.y - __half2float(hy));
        }
        mma16816(dA, gh, bh[0], bh[2]);   // node a (rows 0-7 valid)
        mma16816(dB, gh, bh[1], bh[3]);   // node b (rows 8-15 valid)
        mma16816(dA, gl, bh[0], bh[2]);
        mma16816(dB, gl, bh[1], bh[3]);
        mma16816(dA, gh, bl[0], bl[2]);
        mma16816(dB, gh, bl[1], bl[3]);
    }

    // ---- fixups + softmax (lane holds t=q, s = 2j, 2j+1 for both nodes) ----
    float2 cc = __ldg((const float2*)(g_cts + q*8 + j*2));
    float sA0 = dA[0] + gacc[16][0] + cc.x;
    float sA1 = dA[1] + gacc[16][1] + cc.y;
    float sB0 = dB[2] + gacc[16][2] + cc.x;
    float sB1 = dB[3] + gacc[16][3] + cc.y;
    float mA = fmaxf(sA0, sA1), mB = fmaxf(sB0, sB1);
    mA = fmaxf(mA, __shfl_xor_sync(FULL, mA, 1));
    mA = fmaxf(mA, __shfl_xor_sync(FULL, mA, 2));
    mB = fmaxf(mB, __shfl_xor_sync(FULL, mB, 1));
    mB = fmaxf(mB, __shfl_xor_sync(FULL, mB, 2));
    float eA0 = expf(sA0 - mA), eA1 = expf(sA1 - mA);
    float eB0 = expf(sB0 - mB), eB1 = expf(sB1 - mB);
    float zA = eA0 + eA1, zB = eB0 + eB1;
    zA += __shfl_xor_sync(FULL, zA, 1); zA += __shfl_xor_sync(FULL, zA, 2);
    zB += __shfl_xor_sync(FULL, zB, 1); zB += __shfl_xor_sync(FULL, zB, 2);
    float iA = 1.f/zA, iB = 1.f/zB;
    uint32_t paPk = packf(eA0*iA, eA1*iA);
    uint32_t pbPk = packf(eB0*iB, eB1*iB);

    // ---- PA = P @ A  (m16n8k8; zero a-frags kill cross-node garbage) ----
    float pacc[16][4] = {};
    {
        const int off = (lane & 3)*16 + (lane >> 2);
#pragma unroll
        for (int nt = 0; nt < 16; nt++) {
            int ktA = nt >> 1, kg = nt & 1;
            const float* bsA = aW + (ktA*4 + kg*2 + 0)*64;
            const float* bsB = aW + (ktA*4 + kg*2 + 1)*64;
            uint32_t bfa = packf(bsA[off], bsA[off + 8]);
            uint32_t bfb = packf(bsB[off], bsB[off + 8]);
            mma1688(pacc[nt], paPk, 0u, bfa);
            mma1688(pacc[nt], 0u, pbPk, bfb);
        }
    }

    // ---- O = [PA | P] @ [Wv ; cv]  (9 kt aug, 1-pass) ----
    float oacc[16][4] = {};
    {
        const uint2* wv2 = (const uint2*)g_wvF;
#pragma unroll
        for (int kt = 0; kt < 9; kt++) {
            uint32_t af[4];
            if (kt < 8) {
                af[0] = packf(pacc[2*kt][0],   pacc[2*kt][1]);
                af[1] = packf(pacc[2*kt][2],   pacc[2*kt][3]);
                af[2] = packf(pacc[2*kt+1][0], pacc[2*kt+1][1]);
                af[3] = packf(pacc[2*kt+1][2], pacc[2*kt+1][3]);
            } else {
                af[0] = paPk; af[1] = pbPk; af[2] = 0u; af[3] = 0u;
            }
#pragma unroll
            for (int nt = 0; nt < 16; nt++) {
                uint2 b = __ldg(&wv2[(nt*9 + kt)*32 + lane]);
                mma16816(oacc[nt], af, b.x, b.y);
            }
        }
    }

    // ---- stage x frags (overwrites aW) + res GEMM (1-pass) ----
    __syncwarp();
#pragma unroll
    for (int kt = 0; kt < 4; kt++)
#pragma unroll
        for (int p = 0; p < 4; p++) {
            int node = (p & 1) ? nb : na;
            int k = kt*16 + ((p >> 1) & 1)*8 + j*2;
            *(float2*)(aW + (kt*4 + p)*64 + lane*2) =
                *(const float2*)(x + ((size_t)q*NN + node)*NIN + k);
        }
    __syncwarp();
    float racc[16][4] = {};
    wgemm<4, 16, 1>(racc, aW, g_wrF, lane);

    // ---- epilogue: relu/gate/LN/store ----
    float alpha = 1.f / (1.f + expf(-__ldg(res_alpha)));
    float beta = 1.f - alpha;
    float sua = 0.f, sqa = 0.f, sub = 0.f, sqb = 0.f;
#pragma unroll
    for (int nt = 0; nt < 16; nt++) {
        int c = nt*8 + j*2;
        float2 fb = __ldg((const float2*)(fc_b + c));
        float2 rb = __ldg((const float2*)(res_b + c));
        float v0 = fmaxf(oacc[nt][0]*WSCALE_INV + fb.x, 0.f)*alpha +
                   (racc[nt][0]*WSCALE_INV + rb.x)*beta;
        float v1 = fmaxf(oacc[nt][1]*WSCALE_INV + fb.y, 0.f)*alpha +
                   (racc[nt][1]*WSCALE_INV + rb.y)*beta;
        float v2 = fmaxf(oacc[nt][2]*WSCALE_INV + fb.x, 0.f)*alpha +
                   (racc[nt][2]*WSCALE_INV + rb.x)*beta;
        float v3 = fmaxf(oacc[nt][3]*WSCALE_INV + fb.y, 0.f)*alpha +
                   (racc[nt][3]*WSCALE_INV + rb.y)*beta;
        oacc[nt][0] = v0; oacc[nt][1] = v1; oacc[nt][2] = v2; oacc[nt][3] = v3;
        sua += v0 + v1; sqa += v0*v0 + v1*v1;
        sub += v2 + v3; sqb += v2*v2 + v3*v3;
    }
    sua += __shfl_xor_sync(FULL, sua, 1); sua += __shfl_xor_sync(FULL, sua, 2);
    sqa += __shfl_xor_sync(FULL, sqa, 1); sqa += __shfl_xor_sync(FULL, sqa, 2);
    sub += __shfl_xor_sync(FULL, sub, 1); sub += __shfl_xor_sync(FULL, sub, 2);
    sqb += __shfl_xor_sync(FULL, sqb, 1); sqb += __shfl_xor_sync(FULL, sqb, 2);
    float mua = sua * (1.f/128.f);
    float mub = sub * (1.f/128.f);
    float inva = rsqrtf(sqa*(1.f/128.f) - mua*mua + LN_EPS);
    float invb = rsqrtf(sqb*(1.f/128.f) - mub*mub + LN_EPS);

    float* outa = out + ((size_t)q*NN + na)*H;
    float* outb = out + ((size_t)q*NN + nb)*H;
#pragma unroll
    for (int nt = 0; nt < 16; nt++) {
        int c = nt*8 + j*2;
        float2 lg = __ldg((const float2*)(ln_g + c));
        float2 lb = __ldg((const float2*)(ln_b + c));
        float2 oa = make_float2((oacc[nt][0] - mua)*inva*lg.x + lb.x,
                                (oacc[nt][1] - mua)*inva*lg.y + lb.y);
        float2 ob = make_float2((oacc[nt][2] - mub)*invb*lg.x + lb.x,
                                (oacc[nt][3] - mub)*invb*lg.y + lb.y);
        *(float2*)(outa + c) = oa;
        *(float2*)(outb + c) = ob;
    }
}

extern "C" void kernel_launch(void* const* d_in, const int* in_sizes, int n_in,
                              void* d_out, int out_size) {
    (void)in_sizes; (void)n_in; (void)out_size;
    const float* inter     = (const float*)d_in[0];
    const float* x         = (const float*)d_in[1];
    const float* proj_w    = (const float*)d_in[2];
    const float* proj_b    = (const float*)d_in[3];
    const float* q_w       = (const float*)d_in[4];
    const float* k_w       = (const float*)d_in[5];
    const float* v_w       = (const float*)d_in[6];
    const float* fc_w      = (const float*)d_in[7];
    const float* fc_b      = (const float*)d_in[8];
    const float* res_w     = (const float*)d_in[9];
    const float* res_b     = (const float*)d_in[10];
    const float* res_alpha = (const float*)d_in[11];
    const float* ln_g      = (const float*)d_in[12];
    const float* ln_b      = (const float*)d_in[13];
    float* out = (float*)d_out;

    cudaFuncSetAttribute(htgnn_main, cudaFuncAttributeMaxDynamicSharedMemorySize,
                         65536);

    prep0_kernel<<<T, H>>>(proj_b);
    prep1_kernel<<<H, 512>>>(proj_w, q_w, k_w, v_w, res_w);
    prep2_kernel<<<H, 512>>>(fc_w);
    prep3_kernel<<<H, 512>>>();
    htgnn_main<<<NN/16, 256, 65536>>>(inter, x, fc_b, res_b, res_alpha,
                                      ln_g, ln_b, out);
}